// round 5
// baseline (speedup 1.0000x reference)
#include <cuda_runtime.h>

// ---------------- problem constants (fixed shapes) ----------------
#define NN     100000      // nodes
#define NE     3200000     // edges
#define F      116         // input feature dim
#define F4     29          // F / 4 (116 = 29 float4)
#define H      256         // hidden dim
#define SLOTS  96          // ELL capacity per node (Poisson(32); P(overflow)~1e-13)
#define OVFCAP 8192
#define NPAD   100096      // padded rows for GEMM tiles

#define BM 64
#define APITCH 68          // padded lead dim for transposed A tile
#define GEMM_SMEM ((F*APITCH + F*H) * 4)   // 150336 bytes

// ---------------- device scratch (no allocations allowed) ----------------
__device__ int   g_cnt[NN];
__device__ int   g_ell[(long long)NN * SLOTS];   // 38.4 MB, L2-resident
__device__ float g_dinv[NN];
__device__ float g_agg[(long long)NPAD * F];     // rows < NN fully overwritten each run
__device__ int   g_ovf_cnt;
__device__ int   g_ovf[OVFCAP * 2];

// ---------------- packed fp32x2 helpers (full-rate fp32 on sm_103a) -------
__device__ __forceinline__ void ffma2(unsigned long long& d,
                                      unsigned long long a,
                                      unsigned long long b) {
    asm("fma.rn.f32x2 %0, %1, %2, %3;" : "=l"(d) : "l"(a), "l"(b), "l"(d));
}
__device__ __forceinline__ unsigned long long dup2(float v) {
    unsigned long long r;
    asm("mov.b64 %0, {%1, %1};" : "=l"(r) : "f"(v));
    return r;
}
__device__ __forceinline__ float2 unpk(unsigned long long v) {
    float2 r;
    asm("mov.b64 {%0, %1}, %2;" : "=f"(r.x), "=f"(r.y) : "l"(v));
    return r;
}

// ---------------- 1. init: self loop seeds ELL, cnt=1 ----------------
__global__ void k_init() {
    int v = blockIdx.x * blockDim.x + threadIdx.x;
    if (v < NN) {
        g_cnt[v] = 1;
        g_ell[v * SLOTS] = v;
        if (v == 0) g_ovf_cnt = 0;
    }
}

// ---------------- 2. fill: bucket edges by dst ----------------
__global__ void k_fill(const int* __restrict__ ei) {
    int e = blockIdx.x * blockDim.x + threadIdx.x;
    if (e >= NE) return;
    int s = ei[e];
    int d = ei[NE + e];
    int p = atomicAdd(&g_cnt[d], 1);
    if (p < SLOTS) {
        g_ell[d * SLOTS + p] = s;
    } else {
        int o = atomicAdd(&g_ovf_cnt, 1);
        if (o < OVFCAP) { g_ovf[2*o] = s; g_ovf[2*o + 1] = d; }
    }
}

// ---------------- 3. dinv = rsqrt(deg) ----------------
__global__ void k_dinv() {
    int v = blockIdx.x * blockDim.x + threadIdx.x;
    if (v < NN) g_dinv[v] = rsqrtf((float)g_cnt[v]);   // deg >= 1 (self loop)
}

// ---------------- 4. gather: warp per node, float4 lanes, fold dinv[src] ---
// Neighbor list consumed as int4 (ELL rows are 384B, 16B-aligned).
__global__ void k_gather(const float* __restrict__ x) {
    int warp = (blockIdx.x * blockDim.x + threadIdx.x) >> 5;
    if (warp >= NN) return;
    int lane = threadIdx.x & 31;
    bool act = lane < F4;

    int cnt = g_cnt[warp];
    if (cnt > SLOTS) cnt = SLOTS;
    const int*  lst  = &g_ell[warp * SLOTS];
    const int4* lst4 = (const int4*)lst;
    const float4* x4 = (const float4*)x;

    float4 a0 = make_float4(0.f,0.f,0.f,0.f);
    float4 a1 = a0, a2 = a0, a3 = a0;

    int nq = cnt >> 2;          // full groups of 4
    for (int q = 0; q < nq; q++) {
        int4 n = lst4[q];       // one LDG.128, uniform broadcast
        if (act) {
            float  d0 = g_dinv[n.x], d1 = g_dinv[n.y];
            float  d2 = g_dinv[n.z], d3 = g_dinv[n.w];
            float4 v0 = x4[n.x * F4 + lane];
            float4 v1 = x4[n.y * F4 + lane];
            float4 v2 = x4[n.z * F4 + lane];
            float4 v3 = x4[n.w * F4 + lane];
            a0.x += v0.x*d0; a0.y += v0.y*d0; a0.z += v0.z*d0; a0.w += v0.w*d0;
            a1.x += v1.x*d1; a1.y += v1.y*d1; a1.z += v1.z*d1; a1.w += v1.w*d1;
            a2.x += v2.x*d2; a2.y += v2.y*d2; a2.z += v2.z*d2; a2.w += v2.w*d2;
            a3.x += v3.x*d3; a3.y += v3.y*d3; a3.z += v3.z*d3; a3.w += v3.w*d3;
        }
    }
    for (int j = nq << 2; j < cnt; j++) {
        int n0 = lst[j];
        if (act) {
            float  d0 = g_dinv[n0];
            float4 v0 = x4[n0 * F4 + lane];
            a0.x += v0.x*d0; a0.y += v0.y*d0; a0.z += v0.z*d0; a0.w += v0.w*d0;
        }
    }
    if (act) {
        float4 r;
        r.x = (a0.x + a1.x) + (a2.x + a3.x);
        r.y = (a0.y + a1.y) + (a2.y + a3.y);
        r.z = (a0.z + a1.z) + (a2.z + a3.z);
        r.w = (a0.w + a1.w) + (a2.w + a3.w);
        ((float4*)g_agg)[warp * F4 + lane] = r;
    }
}

// ---------------- 4b. overflow scatter (normally zero work) ----------------
__global__ void k_ovf(const float* __restrict__ x) {
    int m = g_ovf_cnt;
    if (m > OVFCAP) m = OVFCAP;
    for (int i = blockIdx.x; i < m; i += gridDim.x) {
        int s = g_ovf[2*i], d = g_ovf[2*i + 1];
        float ds = g_dinv[s];
        if (threadIdx.x < F)
            atomicAdd(&g_agg[d * F + threadIdx.x], x[s * F + threadIdx.x] * ds);
    }
}

// ---------------- 5. GEMM: out = relu(dinv .* (agg @ W) + b) ----------------
__global__ __launch_bounds__(256, 1)
void k_gemm(const float* __restrict__ Wm, const float* __restrict__ bias,
            float* __restrict__ out) {
    extern __shared__ float sm[];
    float* As = sm;               // [F][APITCH], transposed A tile
    float* Bs = sm + F * APITCH;  // [F][H]

    const int t = threadIdx.x;
    const int R = blockIdx.x * BM;

    // load W (whole 116x256) -> Bs, float4 coalesced
    const float4* W4 = (const float4*)Wm;
    float4* Bs4 = (float4*)Bs;
#pragma unroll
    for (int i = 0; i < (F * H / 4) / 256; i++)   // 29 iters
        Bs4[i * 256 + t] = W4[i * 256 + t];

    // load A tile (64 rows x 116), transpose into As[k][row]
    const float* Ag = g_agg + (long long)R * F;
#pragma unroll
    for (int i = 0; i < (BM * F) / 256; i++) {    // 29 iters
        int idx = i * 256 + t;
        int row = idx / F;
        int k = idx - row * F;
        As[k * APITCH + row] = Ag[idx];
    }
    __syncthreads();

    const int tx = t & 31;
    const int ty = t >> 5;

    // acc pairs: acc2[i][p] holds cols {2p,2p+1} within this thread's 8 cols
    unsigned long long acc2[8][4];
#pragma unroll
    for (int i = 0; i < 8; i++)
#pragma unroll
        for (int p = 0; p < 4; p++) acc2[i][p] = 0ull;

#pragma unroll 4
    for (int k = 0; k < F; k++) {
        float4 fa0 = *(const float4*)(As + k * APITCH + ty * 4);
        float4 fa1 = *(const float4*)(As + k * APITCH + ty * 4 + 32);
        ulonglong2 b01 = *(const ulonglong2*)(Bs + k * H + tx * 4);
        ulonglong2 b23 = *(const ulonglong2*)(Bs + k * H + tx * 4 + 128);
        unsigned long long bp0 = b01.x, bp1 = b01.y, bp2 = b23.x, bp3 = b23.y;
        float av[8] = {fa0.x, fa0.y, fa0.z, fa0.w, fa1.x, fa1.y, fa1.z, fa1.w};
#pragma unroll
        for (int i = 0; i < 8; i++) {
            unsigned long long ad = dup2(av[i]);
            ffma2(acc2[i][0], ad, bp0);
            ffma2(acc2[i][1], ad, bp1);
            ffma2(acc2[i][2], ad, bp2);
            ffma2(acc2[i][3], ad, bp3);
        }
    }

    float4 bb0 = ((const float4*)bias)[tx];
    float4 bb1 = ((const float4*)bias)[tx + 32];

#pragma unroll
    for (int i = 0; i < 8; i++) {
        int r = (i < 4) ? (ty * 4 + i) : (32 + ty * 4 + (i - 4));
        int gr = R + r;
        if (gr >= NN) continue;
        float di = g_dinv[gr];
        float2 p0 = unpk(acc2[i][0]);
        float2 p1 = unpk(acc2[i][1]);
        float2 p2 = unpk(acc2[i][2]);
        float2 p3 = unpk(acc2[i][3]);
        float4 o0, o1;
        o0.x = fmaxf(p0.x * di + bb0.x, 0.f);
        o0.y = fmaxf(p0.y * di + bb0.y, 0.f);
        o0.z = fmaxf(p1.x * di + bb0.z, 0.f);
        o0.w = fmaxf(p1.y * di + bb0.w, 0.f);
        o1.x = fmaxf(p2.x * di + bb1.x, 0.f);
        o1.y = fmaxf(p2.y * di + bb1.y, 0.f);
        o1.z = fmaxf(p3.x * di + bb1.z, 0.f);
        o1.w = fmaxf(p3.y * di + bb1.w, 0.f);
        float4* orow = (float4*)(out + (long long)gr * H);
        orow[tx] = o0;
        orow[tx + 32] = o1;
    }
}

// ---------------- launch ----------------
extern "C" void kernel_launch(void* const* d_in, const int* in_sizes, int n_in,
                              void* d_out, int out_size) {
    const float* x  = (const float*)d_in[0];
    const int*   ei = (const int*)d_in[1];
    const float* W  = (const float*)d_in[2];
    const float* b  = (const float*)d_in[3];
    float* out = (float*)d_out;
    (void)in_sizes; (void)n_in; (void)out_size;

    cudaFuncSetAttribute(k_gemm, cudaFuncAttributeMaxDynamicSharedMemorySize,
                         GEMM_SMEM);

    k_init  <<<(NN + 255) / 256, 256>>>();
    k_fill  <<<(NE + 255) / 256, 256>>>(ei);
    k_dinv  <<<(NN + 255) / 256, 256>>>();
    k_gather<<<(NN + 7) / 8, 256>>>(x);
    k_ovf   <<<64, 128>>>(x);
    k_gemm  <<<(NN + BM - 1) / BM, 256, GEMM_SMEM>>>(W, b, out);
}

// round 12
// speedup vs baseline: 1.1108x; 1.1108x over previous
#include <cuda_runtime.h>

// ---------------- problem constants (fixed shapes) ----------------
#define NN     100000      // nodes
#define NE     3200000     // edges
#define F      116         // input feature dim
#define F4     29          // F / 4 (116 = 29 float4)
#define H      256         // hidden dim
#define SLOTS  96          // ELL capacity per node (Poisson(32); P(overflow)~1e-13)
#define OVFCAP 8192
#define NPAD   100096      // padded rows for GEMM tiles

#define BM 64
#define BN 128             // N-split: 2 col-halves -> 2 CTAs/SM
#define APITCH 68          // padded lead dim for transposed A tile
#define GEMM_SMEM ((F*APITCH + F*BN) * 4)   // 90944 bytes -> 2 CTAs/SM

// ---------------- device scratch (no allocations allowed) ----------------
__device__ int   g_cnt[NN];
__device__ int   g_ell[(long long)NN * SLOTS];   // 38.4 MB, L2-resident
__device__ float g_dinv[NN];
__device__ float g_agg[(long long)NPAD * F];     // rows < NN fully overwritten each run
__device__ int   g_ovf_cnt;
__device__ int   g_ovf[OVFCAP * 2];

// ---------------- packed fp32x2 helpers (full-rate fp32 on sm_103a) -------
__device__ __forceinline__ void ffma2(unsigned long long& d,
                                      unsigned long long a,
                                      unsigned long long b) {
    asm("fma.rn.f32x2 %0, %1, %2, %3;" : "=l"(d) : "l"(a), "l"(b), "l"(d));
}
__device__ __forceinline__ unsigned long long dup2(float v) {
    unsigned long long r;
    asm("mov.b64 %0, {%1, %1};" : "=l"(r) : "f"(v));
    return r;
}
__device__ __forceinline__ float2 unpk(unsigned long long v) {
    float2 r;
    asm("mov.b64 {%0, %1}, %2;" : "=f"(r.x), "=f"(r.y) : "l"(v));
    return r;
}

// ---------------- 1. init: self loop seeds ELL, cnt=1 ----------------
__global__ void k_init() {
    int v = blockIdx.x * blockDim.x + threadIdx.x;
    if (v < NN) {
        g_cnt[v] = 1;
        g_ell[v * SLOTS] = v;
        if (v == 0) g_ovf_cnt = 0;
    }
}

// ---------------- 2. fill: bucket edges by dst ----------------
__global__ void k_fill(const int* __restrict__ ei) {
    int e = blockIdx.x * blockDim.x + threadIdx.x;
    if (e >= NE) return;
    int s = ei[e];
    int d = ei[NE + e];
    int p = atomicAdd(&g_cnt[d], 1);
    if (p < SLOTS) {
        g_ell[d * SLOTS + p] = s;
    } else {
        int o = atomicAdd(&g_ovf_cnt, 1);
        if (o < OVFCAP) { g_ovf[2*o] = s; g_ovf[2*o + 1] = d; }
    }
}

// ---------------- 3. dinv = rsqrt(deg) ----------------
__global__ void k_dinv() {
    int v = blockIdx.x * blockDim.x + threadIdx.x;
    if (v < NN) g_dinv[v] = rsqrtf((float)g_cnt[v]);   // deg >= 1 (self loop)
}

// ---------------- 4. gather: warp per node, float4 lanes, fold dinv[src] ---
// 64-thread blocks (straggler fix) + software-pipelined int4 index prefetch.
__global__ __launch_bounds__(64)
void k_gather(const float* __restrict__ x) {
    int warp = (blockIdx.x * blockDim.x + threadIdx.x) >> 5;
    if (warp >= NN) return;
    int lane = threadIdx.x & 31;
    bool act = lane < F4;

    int cnt = g_cnt[warp];
    if (cnt > SLOTS) cnt = SLOTS;
    const int*  lst  = &g_ell[warp * SLOTS];
    const int4* lst4 = (const int4*)lst;
    const float4* x4 = (const float4*)x;

    float4 a0 = make_float4(0.f,0.f,0.f,0.f);
    float4 a1 = a0, a2 = a0, a3 = a0;

    int nq = cnt >> 2;          // full groups of 4
    if (nq > 0) {
        int4 n = lst4[0];       // head of software pipeline
        for (int q = 0; q < nq; q++) {
            int4 nn = (q + 1 < nq) ? lst4[q + 1] : n;  // prefetch next indices
            if (act) {
                float  d0 = g_dinv[n.x], d1 = g_dinv[n.y];
                float  d2 = g_dinv[n.z], d3 = g_dinv[n.w];
                float4 v0 = x4[n.x * F4 + lane];
                float4 v1 = x4[n.y * F4 + lane];
                float4 v2 = x4[n.z * F4 + lane];
                float4 v3 = x4[n.w * F4 + lane];
                a0.x += v0.x*d0; a0.y += v0.y*d0; a0.z += v0.z*d0; a0.w += v0.w*d0;
                a1.x += v1.x*d1; a1.y += v1.y*d1; a1.z += v1.z*d1; a1.w += v1.w*d1;
                a2.x += v2.x*d2; a2.y += v2.y*d2; a2.z += v2.z*d2; a2.w += v2.w*d2;
                a3.x += v3.x*d3; a3.y += v3.y*d3; a3.z += v3.z*d3; a3.w += v3.w*d3;
            }
            n = nn;
        }
    }
    for (int j = nq << 2; j < cnt; j++) {
        int n0 = lst[j];
        if (act) {
            float  d0 = g_dinv[n0];
            float4 v0 = x4[n0 * F4 + lane];
            a0.x += v0.x*d0; a0.y += v0.y*d0; a0.z += v0.z*d0; a0.w += v0.w*d0;
        }
    }
    if (act) {
        float4 r;
        r.x = (a0.x + a1.x) + (a2.x + a3.x);
        r.y = (a0.y + a1.y) + (a2.y + a3.y);
        r.z = (a0.z + a1.z) + (a2.z + a3.z);
        r.w = (a0.w + a1.w) + (a2.w + a3.w);
        ((float4*)g_agg)[warp * F4 + lane] = r;
    }
}

// ---------------- 4b. overflow scatter (normally zero work) ----------------
__global__ void k_ovf(const float* __restrict__ x) {
    int m = g_ovf_cnt;
    if (m > OVFCAP) m = OVFCAP;
    for (int i = blockIdx.x; i < m; i += gridDim.x) {
        int s = g_ovf[2*i], d = g_ovf[2*i + 1];
        float ds = g_dinv[s];
        if (threadIdx.x < F)
            atomicAdd(&g_agg[d * F + threadIdx.x], x[s * F + threadIdx.x] * ds);
    }
}

// ---------------- 5. GEMM: out = relu(dinv .* (agg @ W) + b) ----------------
// BM=64 x BN=128 tiles, 2 CTAs/SM; thread = 8 rows x 4 cols.
__global__ __launch_bounds__(256, 2)
void k_gemm(const float* __restrict__ Wm, const float* __restrict__ bias,
            float* __restrict__ out) {
    extern __shared__ float sm[];
    float* As = sm;               // [F][APITCH], transposed A tile
    float* Bs = sm + F * APITCH;  // [F][BN]

    const int t  = threadIdx.x;
    const int R  = blockIdx.x * BM;
    const int C  = blockIdx.y * BN;   // 0 or 128

    // load W column-half (116 x 128) -> Bs, float4 coalesced
    {
        const float4* W4 = (const float4*)Wm;
        float4* Bs4 = (float4*)Bs;
        int cbase = C >> 2;           // float4 col offset in W row
#pragma unroll
        for (int i = 0; i < 14; i++) {        // 14*256 = 3584
            int idx = i * 256 + t;
            int k   = idx >> 5;               // 32 float4 per Bs row
            int c4  = idx & 31;
            Bs4[idx] = W4[k * (H/4) + cbase + c4];
        }
        int idx = 14 * 256 + t;               // remaining 128
        if (idx < F * (BN/4)) {
            int k  = idx >> 5;
            int c4 = idx & 31;
            Bs4[idx] = W4[k * (H/4) + cbase + c4];
        }
    }

    // load A tile (64 rows x 116), transpose into As[k][row]
    const float* Ag = g_agg + (long long)R * F;
#pragma unroll
    for (int i = 0; i < (BM * F) / 256; i++) {    // 29 iters
        int idx = i * 256 + t;
        int row = idx / F;
        int k = idx - row * F;
        As[k * APITCH + row] = Ag[idx];
    }
    __syncthreads();

    const int tx = t & 31;       // col group: 4 floats at tx*4
    const int ty = t >> 5;       // row group: 8 rows at ty*8

    unsigned long long acc2[8][2];
#pragma unroll
    for (int i = 0; i < 8; i++) { acc2[i][0] = 0ull; acc2[i][1] = 0ull; }

#pragma unroll 4
    for (int k = 0; k < F; k++) {
        float4 fa0 = *(const float4*)(As + k * APITCH + ty * 8);
        float4 fa1 = *(const float4*)(As + k * APITCH + ty * 8 + 4);
        ulonglong2 bp = *(const ulonglong2*)(Bs + k * BN + tx * 4);
        float av[8] = {fa0.x, fa0.y, fa0.z, fa0.w, fa1.x, fa1.y, fa1.z, fa1.w};
#pragma unroll
        for (int i = 0; i < 8; i++) {
            unsigned long long ad = dup2(av[i]);
            ffma2(acc2[i][0], ad, bp.x);
            ffma2(acc2[i][1], ad, bp.y);
        }
    }

    float4 bb = *(const float4*)(bias + C + tx * 4);

#pragma unroll
    for (int i = 0; i < 8; i++) {
        int gr = R + ty * 8 + i;
        if (gr >= NN) continue;
        float di = g_dinv[gr];
        float2 p0 = unpk(acc2[i][0]);
        float2 p1 = unpk(acc2[i][1]);
        float4 o;
        o.x = fmaxf(p0.x * di + bb.x, 0.f);
        o.y = fmaxf(p0.y * di + bb.y, 0.f);
        o.z = fmaxf(p1.x * di + bb.z, 0.f);
        o.w = fmaxf(p1.y * di + bb.w, 0.f);
        *(float4*)(out + (long long)gr * H + C + tx * 4) = o;
    }
}

// ---------------- launch ----------------
extern "C" void kernel_launch(void* const* d_in, const int* in_sizes, int n_in,
                              void* d_out, int out_size) {
    const float* x  = (const float*)d_in[0];
    const int*   ei = (const int*)d_in[1];
    const float* W  = (const float*)d_in[2];
    const float* b  = (const float*)d_in[3];
    float* out = (float*)d_out;
    (void)in_sizes; (void)n_in; (void)out_size;

    cudaFuncSetAttribute(k_gemm, cudaFuncAttributeMaxDynamicSharedMemorySize,
                         GEMM_SMEM);

    k_init  <<<(NN + 255) / 256, 256>>>();
    k_fill  <<<(NE + 255) / 256, 256>>>(ei);
    k_dinv  <<<(NN + 255) / 256, 256>>>();
    k_gather<<<(NN * 32 + 63) / 64, 64>>>(x);
    k_ovf   <<<64, 128>>>(x);
    dim3 ggrid((NN + BM - 1) / BM, H / BN);   // (1563, 2)
    k_gemm  <<<ggrid, 256, GEMM_SMEM>>>(W, b, out);
}